// round 14
// baseline (speedup 1.0000x reference)
#include <cuda_runtime.h>
#include <cuda_bf16.h>

// Problem constants (HawkesIntensityFunction: B=2, N=4096, D=256)
#define BATCH 2
#define NLEN  4096
#define DM    256
#define LOG2E 1.4426950408889634f

#define ROWS_PB 256          // rows per block (== blockDim.x)
#define TJ      64           // j-tile size (events in smem)
#define RT_CNT  (NLEN / ROWS_PB)             // 16 row tiles per batch
#define JT_CNT  (NLEN / TJ)                  // 64 j tiles per batch
#define BLOCKS_PER_BATCH 544                 // sum_{rt=0..15} (64 - 4*rt)
#define GRID_K1 (2 * BLOCKS_PER_BATCH)       // 1088

__device__ __forceinline__ float ex2_approx(float x) {
    float r; asm("ex2.approx.f32 %0, %1;" : "=f"(r) : "f"(x)); return r;
}
__device__ __forceinline__ float sqrt_approx(float x) {
    float r; asm("sqrt.approx.f32 %0, %1;" : "=f"(r) : "f"(x)); return r;
}

// Scratch (static zero-init; combiner resets after use so graph replays
// start clean). g_cnt[i] counts contributions: (64-4*rt) pair blocks + 1 dot.
__device__ float g_base  [BATCH * NLEN];
__device__ float g_excite[BATCH * NLEN];
__device__ int   g_cnt   [BATCH * NLEN];

// pair term vs tile event v for row at (px,py): 2^{ng2*dist - u_j}
__device__ __forceinline__ float pair_term(float px, float py, float ng2,
                                           const float4& v)
{
    const float dx = px - v.x;
    const float dy = py - v.y;
    const float sq = fmaf(dx, dx, dy * dy);
    return ex2_approx(fmaf(ng2, sqrt_approx(sq), v.w));
}

// Last-arriver combine for one row (gidx = b*NLEN + i).
// out[i] = mu + exp(dot+b) + alpha*(i+1) + alpha*2^{u_i}*excite
// (alpha*(i+1) = closed form of j<=i masked entries: triu mask applied BEFORE
// exp in the reference, so each contributes exp(0)*exp(0)=1.)
__device__ __noinline__ void combine_row(int gidx, int i,
                                         float muv, float av, float bv, float nb2,
                                         const float* __restrict__ t,
                                         float* __restrict__ out)
{
    __threadfence();                       // acquire: all contributors' data visible
    const float dot = g_base[gidx];
    const float exc = g_excite[gidx];
    const float base = ex2_approx((dot + bv) * LOG2E);
    const float ui   = nb2 * __ldg(t + gidx);
    out[gidx] = muv + base + av * ((float)(i + 1) + ex2_approx(ui) * exc);
    g_excite[gidx] = 0.0f;                 // reset scratch for next replay
    g_cnt[gidx]    = 0;
}

// ---------------------------------------------------------------------------
// Single fused kernel: pairs + base dots + last-arriver combine.
// Grid = 1088 triangular tiles (256 rows/block, TJ=64).
// Blocks 0..1023 also compute base dots for rows blockIdx*8+warp (z loads
// issued before the pair loop -> DRAM latency hidden under MUFU work).
// ---------------------------------------------------------------------------
__global__ __launch_bounds__(256)
void hawkes_fused_kernel(const float* __restrict__ z,
                         const float* __restrict__ t,
                         const float* __restrict__ loc,
                         const float* __restrict__ w,
                         const float* __restrict__ bias,
                         const float* __restrict__ mu,
                         const float* __restrict__ alpha,
                         const float* __restrict__ beta,
                         const float* __restrict__ gamma,
                         float* __restrict__ out)
{
    __shared__ float4 tile[TJ];

    const int tid  = threadIdx.x;
    const int lane = tid & 31;
    const int warp = tid >> 5;

    // ---- decode (b, rt, jt); jt >= 4*rt (triangular tile set) ----
    int x = blockIdx.x;
    int b = 0;
    if (x >= BLOCKS_PER_BATCH) { b = 1; x -= BLOCKS_PER_BATCH; }
    int rt = 0;
    #pragma unroll
    for (int k = 0; k < RT_CNT; k++) {
        const int w_k = JT_CNT - 4 * k;
        if (x >= w_k && rt == k) { x -= w_k; rt = k + 1; }
    }
    const int jt = 4 * rt + x;

    const float ng2 = -__ldg(gamma) * LOG2E;
    const float nb2 = -__ldg(beta)  * LOG2E;
    const float muv = __ldg(mu);
    const float av  = __ldg(alpha);
    const float bv  = __ldg(bias);

    // ---- issue base-dot loads early (blocks 0..1023: one row per warp) ----
    const bool do_dot = (blockIdx.x < 1024);
    const int  dg     = blockIdx.x * 8 + warp;     // row id 0..8191
    float4 za0, za1, wv0, wv1;
    if (do_dot) {
        const float4* wr = (const float4*)w;
        const float4* zr = (const float4*)(z + (size_t)dg * DM);
        wv0 = __ldg(wr + lane * 2 + 0);
        wv1 = __ldg(wr + lane * 2 + 1);
        za0 = __ldg(zr + lane * 2 + 0);
        za1 = __ldg(zr + lane * 2 + 1);
    }

    // ---- build tile in smem from raw t/loc ----
    const int rowbase = rt * ROWS_PB;
    const int jbase   = jt * TJ;
    const float*  tb = t + (size_t)b * NLEN;
    const float2* lb = (const float2*)(loc + (size_t)b * NLEN * 2);

    if (tid < TJ) {
        const int j = jbase + tid;
        const float2 lj = __ldg(lb + j);
        const float  uj = nb2 * __ldg(tb + j);
        tile[tid] = make_float4(lj.x, lj.y, 0.0f, -uj);
    }
    __syncthreads();

    // ---- pair loop ----
    const int i = rowbase + tid;
    const float2 li = __ldg(lb + i);
    const float pix = li.x, piy = li.y;

    float a0 = 0.0f, a1 = 0.0f, a2 = 0.0f, a3 = 0.0f;

    if (jbase >= rowbase + ROWS_PB) {
        // interior tile: every j > every i, no masking
        #pragma unroll 4
        for (int jj = 0; jj < TJ; jj += 4) {
            const float4 v0 = tile[jj + 0];
            const float4 v1 = tile[jj + 1];
            const float4 v2 = tile[jj + 2];
            const float4 v3 = tile[jj + 3];
            a0 += pair_term(pix, piy, ng2, v0);
            a1 += pair_term(pix, piy, ng2, v1);
            a2 += pair_term(pix, piy, ng2, v2);
            a3 += pair_term(pix, piy, ng2, v3);
        }
    } else {
        // diagonal tile: keep only j > i
        const int joff = jbase - rowbase;
        for (int jj = 0; jj < TJ; jj += 4) {
            const float4 v0 = tile[jj + 0];
            const float4 v1 = tile[jj + 1];
            const float4 v2 = tile[jj + 2];
            const float4 v3 = tile[jj + 3];
            const float e0 = pair_term(pix, piy, ng2, v0);
            const float e1 = pair_term(pix, piy, ng2, v1);
            const float e2 = pair_term(pix, piy, ng2, v2);
            const float e3 = pair_term(pix, piy, ng2, v3);
            if (joff + jj + 0 > tid) a0 += e0;
            if (joff + jj + 1 > tid) a1 += e1;
            if (joff + jj + 2 > tid) a2 += e2;
            if (joff + jj + 3 > tid) a3 += e3;
        }
    }

    // ---- publish pair contribution, then count arrival ----
    const int gidx = b * NLEN + i;
    atomicAdd(g_excite + gidx, (a0 + a1) + (a2 + a3));
    __threadfence();                                  // release
    {
        const int target = (JT_CNT - 4 * rt) + 1;     // pair blocks + dot
        const int old = atomicAdd(g_cnt + gidx, 1);
        if (old == target - 1)
            combine_row(gidx, i, muv, av, bv, nb2, t, out);
    }

    // ---- finish & publish the base dot (z data long since arrived) ----
    if (do_dot) {
        float dotp;
        dotp = za0.x * wv0.x;
        dotp = fmaf(za0.y, wv0.y, dotp);
        dotp = fmaf(za0.z, wv0.z, dotp);
        dotp = fmaf(za0.w, wv0.w, dotp);
        dotp = fmaf(za1.x, wv1.x, dotp);
        dotp = fmaf(za1.y, wv1.y, dotp);
        dotp = fmaf(za1.z, wv1.z, dotp);
        dotp = fmaf(za1.w, wv1.w, dotp);
        #pragma unroll
        for (int off = 16; off > 0; off >>= 1)
            dotp += __shfl_xor_sync(0xffffffffu, dotp, off);
        if (lane == 0) {
            g_base[dg] = dotp;
            __threadfence();                           // release
            const int i_d  = dg & (NLEN - 1);
            const int rt_d = i_d >> 8;                 // /256
            const int target = (JT_CNT - 4 * rt_d) + 1;
            const int old = atomicAdd(g_cnt + dg, 1);
            if (old == target - 1)
                combine_row(dg, i_d, muv, av, bv, nb2, t, out);
        }
    }
}

extern "C" void kernel_launch(void* const* d_in, const int* in_sizes, int n_in,
                              void* d_out, int out_size)
{
    const float* z     = (const float*)d_in[0];
    const float* t     = (const float*)d_in[1];
    const float* loc   = (const float*)d_in[2];
    const float* w     = (const float*)d_in[3];
    const float* bias  = (const float*)d_in[4];
    const float* mu    = (const float*)d_in[5];
    const float* alpha = (const float*)d_in[6];
    const float* beta  = (const float*)d_in[7];
    const float* gamma = (const float*)d_in[8];
    float* out = (float*)d_out;

    hawkes_fused_kernel<<<GRID_K1, 256>>>(z, t, loc, w, bias, mu, alpha,
                                          beta, gamma, out);
}

// round 15
// speedup vs baseline: 1.1490x; 1.1490x over previous
#include <cuda_runtime.h>
#include <cuda_bf16.h>

// Problem constants (HawkesIntensityFunction: B=2, N=4096, D=256)
#define BATCH 2
#define NLEN  4096
#define DM    256
#define LOG2E 1.4426950408889634f

#define ROWS_PB 256          // rows per block (== blockDim.x)
#define TJ      64           // j-tile size (events in smem)
#define RT_CNT  (NLEN / ROWS_PB)             // 16 row tiles per batch
#define JT_CNT  (NLEN / TJ)                  // 64 j tiles per batch
#define BLOCKS_PER_BATCH 544                 // sum_{rt=0..15} (64 - 4*rt)
#define GRID_K1 (2 * BLOCKS_PER_BATCH)       // 1088

__device__ __forceinline__ float ex2_approx(float x) {
    float r; asm("ex2.approx.f32 %0, %1;" : "=f"(r) : "f"(x)); return r;
}
__device__ __forceinline__ float sqrt_approx(float x) {
    float r; asm("sqrt.approx.f32 %0, %1;" : "=f"(r) : "f"(x)); return r;
}

// pair term vs tile event v for row at (px,py): 2^{ng2*dist - u_j}
__device__ __forceinline__ float pair_term(float px, float py, float ng2,
                                           const float4& v)
{
    const float dx = px - v.x;
    const float dy = py - v.y;
    const float sq = fmaf(dx, dx, dy * dy);
    return ex2_approx(fmaf(ng2, sqrt_approx(sq), v.w));
}

// ---------------------------------------------------------------------------
// Single fused kernel; out must be zeroed before launch (memset graph node).
// out[i] accumulates independent contributions:
//   - each pair block adds  alpha * 2^{u_i} * sum_j 2^{ng2*dist - u_j}
//   - the row's dot warp adds  mu + exp(dot+b) + alpha*(i+1)
// (alpha*(i+1) = closed form of the j<=i masked entries: the triu mask is
// applied BEFORE exp in the reference, so each contributes exp(0)*exp(0)=1.)
// Grid = 1088 triangular tiles (256 rows/block, TJ=64); blocks 0..1023 also
// compute base dots for rows blockIdx*8+warp, with z loads issued before the
// pair loop so the 8MB stream hides under MUFU work.
// ---------------------------------------------------------------------------
__global__ __launch_bounds__(256)
void hawkes_fused_kernel(const float* __restrict__ z,
                         const float* __restrict__ t,
                         const float* __restrict__ loc,
                         const float* __restrict__ w,
                         const float* __restrict__ bias,
                         const float* __restrict__ mu,
                         const float* __restrict__ alpha,
                         const float* __restrict__ beta,
                         const float* __restrict__ gamma,
                         float* __restrict__ out)
{
    __shared__ float4 tile[TJ];

    const int tid  = threadIdx.x;
    const int lane = tid & 31;
    const int warp = tid >> 5;

    // ---- decode (b, rt, jt); jt >= 4*rt (triangular tile set) ----
    int x = blockIdx.x;
    int b = 0;
    if (x >= BLOCKS_PER_BATCH) { b = 1; x -= BLOCKS_PER_BATCH; }
    int rt = 0;
    #pragma unroll
    for (int k = 0; k < RT_CNT; k++) {
        const int w_k = JT_CNT - 4 * k;
        if (x >= w_k && rt == k) { x -= w_k; rt = k + 1; }
    }
    const int jt = 4 * rt + x;

    const float ng2 = -__ldg(gamma) * LOG2E;
    const float nb2 = -__ldg(beta)  * LOG2E;
    const float av  = __ldg(alpha);

    // ---- issue base-dot loads early (blocks 0..1023: one row per warp) ----
    const bool do_dot = (blockIdx.x < 1024);
    const int  dg     = blockIdx.x * 8 + warp;     // row id 0..8191
    float4 za0, za1, wv0, wv1;
    if (do_dot) {
        const float4* wr = (const float4*)w;
        const float4* zr = (const float4*)(z + (size_t)dg * DM);
        wv0 = __ldg(wr + lane * 2 + 0);
        wv1 = __ldg(wr + lane * 2 + 1);
        za0 = __ldg(zr + lane * 2 + 0);
        za1 = __ldg(zr + lane * 2 + 1);
    }

    // ---- build tile in smem from raw t/loc ----
    const int rowbase = rt * ROWS_PB;
    const int jbase   = jt * TJ;
    const float*  tb = t + (size_t)b * NLEN;
    const float2* lb = (const float2*)(loc + (size_t)b * NLEN * 2);

    if (tid < TJ) {
        const int j = jbase + tid;
        const float2 lj = __ldg(lb + j);
        const float  uj = nb2 * __ldg(tb + j);
        tile[tid] = make_float4(lj.x, lj.y, 0.0f, -uj);
    }
    __syncthreads();

    // ---- pair loop ----
    const int i = rowbase + tid;
    const float2 li = __ldg(lb + i);
    const float ui  = nb2 * __ldg(tb + i);         // u_i for this row
    const float pix = li.x, piy = li.y;

    float a0 = 0.0f, a1 = 0.0f, a2 = 0.0f, a3 = 0.0f;

    if (jbase >= rowbase + ROWS_PB) {
        // interior tile: every j > every i, no masking
        #pragma unroll 4
        for (int jj = 0; jj < TJ; jj += 4) {
            const float4 v0 = tile[jj + 0];
            const float4 v1 = tile[jj + 1];
            const float4 v2 = tile[jj + 2];
            const float4 v3 = tile[jj + 3];
            a0 += pair_term(pix, piy, ng2, v0);
            a1 += pair_term(pix, piy, ng2, v1);
            a2 += pair_term(pix, piy, ng2, v2);
            a3 += pair_term(pix, piy, ng2, v3);
        }
    } else {
        // diagonal tile: keep only j > i
        const int joff = jbase - rowbase;
        for (int jj = 0; jj < TJ; jj += 4) {
            const float4 v0 = tile[jj + 0];
            const float4 v1 = tile[jj + 1];
            const float4 v2 = tile[jj + 2];
            const float4 v3 = tile[jj + 3];
            const float e0 = pair_term(pix, piy, ng2, v0);
            const float e1 = pair_term(pix, piy, ng2, v1);
            const float e2 = pair_term(pix, piy, ng2, v2);
            const float e3 = pair_term(pix, piy, ng2, v3);
            if (joff + jj + 0 > tid) a0 += e0;
            if (joff + jj + 1 > tid) a1 += e1;
            if (joff + jj + 2 > tid) a2 += e2;
            if (joff + jj + 3 > tid) a3 += e3;
        }
    }

    // scaled excitation contribution straight into out
    const float acc = (a0 + a1) + (a2 + a3);
    atomicAdd(out + b * NLEN + i, av * ex2_approx(ui) * acc);

    // ---- finish & publish the base dot (z data long since arrived) ----
    if (do_dot) {
        float dotp;
        dotp = za0.x * wv0.x;
        dotp = fmaf(za0.y, wv0.y, dotp);
        dotp = fmaf(za0.z, wv0.z, dotp);
        dotp = fmaf(za0.w, wv0.w, dotp);
        dotp = fmaf(za1.x, wv1.x, dotp);
        dotp = fmaf(za1.y, wv1.y, dotp);
        dotp = fmaf(za1.z, wv1.z, dotp);
        dotp = fmaf(za1.w, wv1.w, dotp);
        #pragma unroll
        for (int off = 16; off > 0; off >>= 1)
            dotp += __shfl_xor_sync(0xffffffffu, dotp, off);
        if (lane == 0) {
            const float muv  = __ldg(mu);
            const float bv   = __ldg(bias);
            const float base = ex2_approx((dotp + bv) * LOG2E);
            const int   i_d  = dg & (NLEN - 1);
            atomicAdd(out + dg, muv + base + av * (float)(i_d + 1));
        }
    }
}

extern "C" void kernel_launch(void* const* d_in, const int* in_sizes, int n_in,
                              void* d_out, int out_size)
{
    const float* z     = (const float*)d_in[0];
    const float* t     = (const float*)d_in[1];
    const float* loc   = (const float*)d_in[2];
    const float* w     = (const float*)d_in[3];
    const float* bias  = (const float*)d_in[4];
    const float* mu    = (const float*)d_in[5];
    const float* alpha = (const float*)d_in[6];
    const float* beta  = (const float*)d_in[7];
    const float* gamma = (const float*)d_in[8];
    float* out = (float*)d_out;

    // zero the accumulator (graph-capturable async memset node)
    cudaMemsetAsync(out, 0, (size_t)out_size * sizeof(float));
    hawkes_fused_kernel<<<GRID_K1, 256>>>(z, t, loc, w, bias, mu, alpha,
                                          beta, gamma, out);
}

// round 16
// speedup vs baseline: 1.2055x; 1.0491x over previous
#include <cuda_runtime.h>
#include <cuda_bf16.h>

// Problem constants (HawkesIntensityFunction: B=2, N=4096, D=256)
#define BATCH 2
#define NLEN  4096
#define DM    256
#define LOG2E 1.4426950408889634f

#define ROWS_PB 256          // rows per block (== blockDim.x)
#define TJ      64           // j-tile size (events in smem)
#define RT_CNT  (NLEN / ROWS_PB)             // 16 row tiles per batch
#define JT_CNT  (NLEN / TJ)                  // 64 j tiles per batch
#define BLOCKS_PER_BATCH 544                 // sum_{rt=0..15} (64 - 4*rt)
#define GRID_K1 (2 * BLOCKS_PER_BATCH)       // 1088

__device__ __forceinline__ float ex2_approx(float x) {
    float r; asm("ex2.approx.f32 %0, %1;" : "=f"(r) : "f"(x)); return r;
}
__device__ __forceinline__ float sqrt_approx(float x) {
    float r; asm("sqrt.approx.f32 %0, %1;" : "=f"(r) : "f"(x)); return r;
}

// pair term vs tile event v for row at (px,py): 2^{ng2*dist - u_j}
__device__ __forceinline__ float pair_term(float px, float py, float ng2,
                                           const float4& v)
{
    const float dx = px - v.x;
    const float dy = py - v.y;
    const float sq = fmaf(dx, dx, dy * dy);
    return ex2_approx(fmaf(ng2, sqrt_approx(sq), v.w));
}

// ---------------------------------------------------------------------------
// K0: zero the output accumulator (cheaper than a cudaMemsetAsync graph node).
// ---------------------------------------------------------------------------
__global__ void hawkes_zero_kernel(float* __restrict__ out)
{
    out[blockIdx.x * 1024 + threadIdx.x] = 0.0f;
}

// ---------------------------------------------------------------------------
// K1: fused pairs + base dots; out accumulates independent contributions:
//   - each pair block adds  alpha * 2^{u_i} * sum_j 2^{ng2*dist - u_j}
//   - the row's dot warp adds  mu + exp(dot+b) + alpha*(i+1)
// (alpha*(i+1) = closed form of the j<=i masked entries: the triu mask is
// applied BEFORE exp in the reference, so each contributes exp(0)*exp(0)=1.)
// Grid = 1088 triangular tiles (256 rows/block, TJ=64); blocks 0..1023 also
// compute base dots for rows blockIdx*8+warp, AFTER the pair loop so the
// z/w registers are not live across the hot loop (regs ~36, occ up).
// ---------------------------------------------------------------------------
__global__ __launch_bounds__(256)
void hawkes_fused_kernel(const float* __restrict__ z,
                         const float* __restrict__ t,
                         const float* __restrict__ loc,
                         const float* __restrict__ w,
                         const float* __restrict__ bias,
                         const float* __restrict__ mu,
                         const float* __restrict__ alpha,
                         const float* __restrict__ beta,
                         const float* __restrict__ gamma,
                         float* __restrict__ out)
{
    __shared__ float4 tile[TJ];

    const int tid  = threadIdx.x;
    const int lane = tid & 31;
    const int warp = tid >> 5;

    // ---- decode (b, rt, jt); jt >= 4*rt (triangular tile set) ----
    int x = blockIdx.x;
    int b = 0;
    if (x >= BLOCKS_PER_BATCH) { b = 1; x -= BLOCKS_PER_BATCH; }
    int rt = 0;
    #pragma unroll
    for (int k = 0; k < RT_CNT; k++) {
        const int w_k = JT_CNT - 4 * k;
        if (x >= w_k && rt == k) { x -= w_k; rt = k + 1; }
    }
    const int jt = 4 * rt + x;

    const float ng2 = -__ldg(gamma) * LOG2E;
    const float nb2 = -__ldg(beta)  * LOG2E;
    const float av  = __ldg(alpha);

    // ---- build tile in smem from raw t/loc ----
    const int rowbase = rt * ROWS_PB;
    const int jbase   = jt * TJ;
    const float*  tb = t + (size_t)b * NLEN;
    const float2* lb = (const float2*)(loc + (size_t)b * NLEN * 2);

    if (tid < TJ) {
        const int j = jbase + tid;
        const float2 lj = __ldg(lb + j);
        const float  uj = nb2 * __ldg(tb + j);
        tile[tid] = make_float4(lj.x, lj.y, 0.0f, -uj);
    }
    __syncthreads();

    // ---- pair loop ----
    const int i = rowbase + tid;
    const float2 li = __ldg(lb + i);
    const float ui  = nb2 * __ldg(tb + i);         // u_i for this row
    const float pix = li.x, piy = li.y;

    float a0 = 0.0f, a1 = 0.0f, a2 = 0.0f, a3 = 0.0f;

    if (jbase >= rowbase + ROWS_PB) {
        // interior tile: every j > every i, no masking
        #pragma unroll 4
        for (int jj = 0; jj < TJ; jj += 4) {
            const float4 v0 = tile[jj + 0];
            const float4 v1 = tile[jj + 1];
            const float4 v2 = tile[jj + 2];
            const float4 v3 = tile[jj + 3];
            a0 += pair_term(pix, piy, ng2, v0);
            a1 += pair_term(pix, piy, ng2, v1);
            a2 += pair_term(pix, piy, ng2, v2);
            a3 += pair_term(pix, piy, ng2, v3);
        }
    } else {
        // diagonal tile: keep only j > i
        const int joff = jbase - rowbase;
        for (int jj = 0; jj < TJ; jj += 4) {
            const float4 v0 = tile[jj + 0];
            const float4 v1 = tile[jj + 1];
            const float4 v2 = tile[jj + 2];
            const float4 v3 = tile[jj + 3];
            const float e0 = pair_term(pix, piy, ng2, v0);
            const float e1 = pair_term(pix, piy, ng2, v1);
            const float e2 = pair_term(pix, piy, ng2, v2);
            const float e3 = pair_term(pix, piy, ng2, v3);
            if (joff + jj + 0 > tid) a0 += e0;
            if (joff + jj + 1 > tid) a1 += e1;
            if (joff + jj + 2 > tid) a2 += e2;
            if (joff + jj + 3 > tid) a3 += e3;
        }
    }

    // scaled excitation contribution straight into out
    const float acc = (a0 + a1) + (a2 + a3);
    atomicAdd(out + b * NLEN + i, av * ex2_approx(ui) * acc);

    // ---- base dot AFTER the pair loop (one latency exposure per block) ----
    if (blockIdx.x < 1024) {
        const int dg = blockIdx.x * 8 + warp;      // row id 0..8191
        const float4* wr = (const float4*)w;
        const float4* zr = (const float4*)(z + (size_t)dg * DM);
        const float4 wv0 = __ldg(wr + lane * 2 + 0);
        const float4 wv1 = __ldg(wr + lane * 2 + 1);
        const float4 za0 = __ldg(zr + lane * 2 + 0);
        const float4 za1 = __ldg(zr + lane * 2 + 1);

        float dotp;
        dotp = za0.x * wv0.x;
        dotp = fmaf(za0.y, wv0.y, dotp);
        dotp = fmaf(za0.z, wv0.z, dotp);
        dotp = fmaf(za0.w, wv0.w, dotp);
        dotp = fmaf(za1.x, wv1.x, dotp);
        dotp = fmaf(za1.y, wv1.y, dotp);
        dotp = fmaf(za1.z, wv1.z, dotp);
        dotp = fmaf(za1.w, wv1.w, dotp);
        #pragma unroll
        for (int off = 16; off > 0; off >>= 1)
            dotp += __shfl_xor_sync(0xffffffffu, dotp, off);

        if (lane == 0) {
            const float muv  = __ldg(mu);
            const float bv   = __ldg(bias);
            const float base = ex2_approx((dotp + bv) * LOG2E);
            const int   i_d  = dg & (NLEN - 1);
            atomicAdd(out + dg, muv + base + av * (float)(i_d + 1));
        }
    }
}

extern "C" void kernel_launch(void* const* d_in, const int* in_sizes, int n_in,
                              void* d_out, int out_size)
{
    const float* z     = (const float*)d_in[0];
    const float* t     = (const float*)d_in[1];
    const float* loc   = (const float*)d_in[2];
    const float* w     = (const float*)d_in[3];
    const float* bias  = (const float*)d_in[4];
    const float* mu    = (const float*)d_in[5];
    const float* alpha = (const float*)d_in[6];
    const float* beta  = (const float*)d_in[7];
    const float* gamma = (const float*)d_in[8];
    float* out = (float*)d_out;

    // K0: zero accumulator (8192 floats)
    hawkes_zero_kernel<<<8, 1024>>>(out);
    // K1: fused pairs + dots
    hawkes_fused_kernel<<<GRID_K1, 256>>>(z, t, loc, w, bias, mu, alpha,
                                          beta, gamma, out);
}

// round 17
// speedup vs baseline: 1.2677x; 1.0516x over previous
#include <cuda_runtime.h>
#include <cuda_bf16.h>

// Problem constants (HawkesIntensityFunction: B=2, N=4096, D=256)
#define BATCH 2
#define NLEN  4096
#define DM    256
#define LOG2E 1.4426950408889634f

#define ROWS_PB 256          // rows per block (== blockDim.x)
#define TJ      64           // j-tile size (events in smem)
#define RT_CNT  (NLEN / ROWS_PB)             // 16 row tiles per batch
#define JT_CNT  (NLEN / TJ)                  // 64 j tiles per batch
#define BLOCKS_PER_BATCH 544                 // sum_{rt=0..15} (64 - 4*rt)
#define GRID_K1 (2 * BLOCKS_PER_BATCH)       // 1088

__device__ __forceinline__ float ex2_approx(float x) {
    float r; asm("ex2.approx.f32 %0, %1;" : "=f"(r) : "f"(x)); return r;
}
__device__ __forceinline__ float sqrt_approx(float x) {
    float r; asm("sqrt.approx.f32 %0, %1;" : "=f"(r) : "f"(x)); return r;
}

// pair term vs tile event v for row at (px,py): 2^{ng2*dist - u_j}
__device__ __forceinline__ float pair_term(float px, float py, float ng2,
                                           const float4& v)
{
    const float dx = px - v.x;
    const float dy = py - v.y;
    const float sq = fmaf(dx, dx, dy * dy);
    return ex2_approx(fmaf(ng2, sqrt_approx(sq), v.w));
}

// ---------------------------------------------------------------------------
// K0: zero the output accumulator. With PDL on K1 this runs entirely under
// K1's pair loop (K1 only waits for it at cudaGridDependencySynchronize()).
// ---------------------------------------------------------------------------
__global__ void hawkes_zero_kernel(float* __restrict__ out)
{
    out[blockIdx.x * 1024 + threadIdx.x] = 0.0f;
}

// ---------------------------------------------------------------------------
// K1: fused pairs + base dots; out accumulates independent contributions:
//   - each pair block adds  alpha * 2^{u_i} * sum_j 2^{ng2*dist - u_j}
//   - the row's dot warp adds  mu + exp(dot+b) + alpha*(i+1)
// (alpha*(i+1) = closed form of the j<=i masked entries: the triu mask is
// applied BEFORE exp in the reference, so each contributes exp(0)*exp(0)=1.)
// Launched with programmatic stream serialization: starts concurrently with
// K0 and only synchronizes (cudaGridDependencySynchronize) before touching
// `out` — the zero pass and the inter-kernel gap disappear from the
// critical path.
// ---------------------------------------------------------------------------
__global__ __launch_bounds__(256)
void hawkes_fused_kernel(const float* __restrict__ z,
                         const float* __restrict__ t,
                         const float* __restrict__ loc,
                         const float* __restrict__ w,
                         const float* __restrict__ bias,
                         const float* __restrict__ mu,
                         const float* __restrict__ alpha,
                         const float* __restrict__ beta,
                         const float* __restrict__ gamma,
                         float* __restrict__ out)
{
    __shared__ float4 tile[TJ];

    const int tid  = threadIdx.x;
    const int lane = tid & 31;
    const int warp = tid >> 5;

    // ---- decode (b, rt, jt); jt >= 4*rt (triangular tile set) ----
    int x = blockIdx.x;
    int b = 0;
    if (x >= BLOCKS_PER_BATCH) { b = 1; x -= BLOCKS_PER_BATCH; }
    int rt = 0;
    #pragma unroll
    for (int k = 0; k < RT_CNT; k++) {
        const int w_k = JT_CNT - 4 * k;
        if (x >= w_k && rt == k) { x -= w_k; rt = k + 1; }
    }
    const int jt = 4 * rt + x;

    const float ng2 = -__ldg(gamma) * LOG2E;
    const float nb2 = -__ldg(beta)  * LOG2E;
    const float av  = __ldg(alpha);

    // ---- build tile in smem from raw t/loc ----
    const int rowbase = rt * ROWS_PB;
    const int jbase   = jt * TJ;
    const float*  tb = t + (size_t)b * NLEN;
    const float2* lb = (const float2*)(loc + (size_t)b * NLEN * 2);

    if (tid < TJ) {
        const int j = jbase + tid;
        const float2 lj = __ldg(lb + j);
        const float  uj = nb2 * __ldg(tb + j);
        tile[tid] = make_float4(lj.x, lj.y, 0.0f, -uj);
    }
    __syncthreads();

    // ---- pair loop ----
    const int i = rowbase + tid;
    const float2 li = __ldg(lb + i);
    const float ui  = nb2 * __ldg(tb + i);         // u_i for this row
    const float pix = li.x, piy = li.y;

    float a0 = 0.0f, a1 = 0.0f, a2 = 0.0f, a3 = 0.0f;

    if (jbase >= rowbase + ROWS_PB) {
        // interior tile: every j > every i, no masking
        #pragma unroll 4
        for (int jj = 0; jj < TJ; jj += 4) {
            const float4 v0 = tile[jj + 0];
            const float4 v1 = tile[jj + 1];
            const float4 v2 = tile[jj + 2];
            const float4 v3 = tile[jj + 3];
            a0 += pair_term(pix, piy, ng2, v0);
            a1 += pair_term(pix, piy, ng2, v1);
            a2 += pair_term(pix, piy, ng2, v2);
            a3 += pair_term(pix, piy, ng2, v3);
        }
    } else {
        // diagonal tile: keep only j > i
        const int joff = jbase - rowbase;
        for (int jj = 0; jj < TJ; jj += 4) {
            const float4 v0 = tile[jj + 0];
            const float4 v1 = tile[jj + 1];
            const float4 v2 = tile[jj + 2];
            const float4 v3 = tile[jj + 3];
            const float e0 = pair_term(pix, piy, ng2, v0);
            const float e1 = pair_term(pix, piy, ng2, v1);
            const float e2 = pair_term(pix, piy, ng2, v2);
            const float e3 = pair_term(pix, piy, ng2, v3);
            if (joff + jj + 0 > tid) a0 += e0;
            if (joff + jj + 1 > tid) a1 += e1;
            if (joff + jj + 2 > tid) a2 += e2;
            if (joff + jj + 3 > tid) a3 += e3;
        }
    }

    // ---- wait for the zero kernel (no-op if launched without PDL) ----
    cudaGridDependencySynchronize();

    // scaled excitation contribution straight into out
    const float acc = (a0 + a1) + (a2 + a3);
    atomicAdd(out + b * NLEN + i, av * ex2_approx(ui) * acc);

    // ---- base dot AFTER the pair loop (one latency exposure per block) ----
    if (blockIdx.x < 1024) {
        const int dg = blockIdx.x * 8 + warp;      // row id 0..8191
        const float4* wr = (const float4*)w;
        const float4* zr = (const float4*)(z + (size_t)dg * DM);
        const float4 wv0 = __ldg(wr + lane * 2 + 0);
        const float4 wv1 = __ldg(wr + lane * 2 + 1);
        const float4 za0 = __ldg(zr + lane * 2 + 0);
        const float4 za1 = __ldg(zr + lane * 2 + 1);

        float dotp;
        dotp = za0.x * wv0.x;
        dotp = fmaf(za0.y, wv0.y, dotp);
        dotp = fmaf(za0.z, wv0.z, dotp);
        dotp = fmaf(za0.w, wv0.w, dotp);
        dotp = fmaf(za1.x, wv1.x, dotp);
        dotp = fmaf(za1.y, wv1.y, dotp);
        dotp = fmaf(za1.z, wv1.z, dotp);
        dotp = fmaf(za1.w, wv1.w, dotp);
        #pragma unroll
        for (int off = 16; off > 0; off >>= 1)
            dotp += __shfl_xor_sync(0xffffffffu, dotp, off);

        if (lane == 0) {
            const float muv  = __ldg(mu);
            const float bv   = __ldg(bias);
            const float base = ex2_approx((dotp + bv) * LOG2E);
            const int   i_d  = dg & (NLEN - 1);
            atomicAdd(out + dg, muv + base + av * (float)(i_d + 1));
        }
    }
}

extern "C" void kernel_launch(void* const* d_in, const int* in_sizes, int n_in,
                              void* d_out, int out_size)
{
    const float* z     = (const float*)d_in[0];
    const float* t     = (const float*)d_in[1];
    const float* loc   = (const float*)d_in[2];
    const float* w     = (const float*)d_in[3];
    const float* bias  = (const float*)d_in[4];
    const float* mu    = (const float*)d_in[5];
    const float* alpha = (const float*)d_in[6];
    const float* beta  = (const float*)d_in[7];
    const float* gamma = (const float*)d_in[8];
    float* out = (float*)d_out;

    // K0: zero accumulator (8192 floats) — hidden under K1 via PDL
    hawkes_zero_kernel<<<8, 1024>>>(out);

    // K1: fused pairs + dots, launched with programmatic stream serialization
    cudaLaunchConfig_t cfg = {};
    cfg.gridDim  = dim3(GRID_K1);
    cfg.blockDim = dim3(256);
    cfg.dynamicSmemBytes = 0;
    cfg.stream   = 0;
    cudaLaunchAttribute attrs[1];
    attrs[0].id = cudaLaunchAttributeProgrammaticStreamSerialization;
    attrs[0].val.programmaticStreamSerializationAllowed = 1;
    cfg.attrs    = attrs;
    cfg.numAttrs = 1;

    cudaError_t err = cudaLaunchKernelEx(&cfg, hawkes_fused_kernel,
                                         z, t, loc, w, bias, mu, alpha,
                                         beta, gamma, out);
    if (err != cudaSuccess) {
        // PDL unavailable in this context: plain launch (stream order provides
        // the zero->fused dependency; the device-side sync is then a no-op).
        hawkes_fused_kernel<<<GRID_K1, 256>>>(z, t, loc, w, bias, mu, alpha,
                                              beta, gamma, out);
    }
}